// round 10
// baseline (speedup 1.0000x reference)
#include <cuda_runtime.h>
#include <math.h>

#define LSEQ   4096
#define DMODEL 1024
#define ORDER  64
#define EMB    5

// ---- scratch (static device globals: allowed) ----
__device__ float  g_h3[LSEQ * ORDER];
__device__ float  g_k [DMODEL * LSEQ];
__device__ float  g_decayA[DMODEL * 64];
__device__ float  g_decayB[DMODEL * 64];
__device__ float2 g_tw[2048];   // quarter table of W8192: w[j]=exp(-2*pi*i*j/8192), j in [0,2048)

// =====================================================================
// Kernel 1: implicit-filter MLP. 2 rows per warp, 8 warps -> 16 rows/CTA.
// grid 256. Also fills decay + twiddle tables.
// =====================================================================
#define MLP_BLOCKS 256
__global__ __launch_bounds__(256) void k_filter_mlp(
    const float* __restrict__ z, const float* __restrict__ deltas,
    const float* __restrict__ W1, const float* __restrict__ b1,
    const float* __restrict__ freq, const float* __restrict__ W2,
    const float* __restrict__ b2, const float* __restrict__ W3,
    const float* __restrict__ b3)
{
    __shared__ float sW1[ORDER * EMB], sb1[ORDER], sb2[ORDER], sb3[ORDER], sfreq[ORDER];
    __shared__ float sW2T[ORDER][ORDER + 1];   // transposed: [j][o]
    __shared__ float sW3T[ORDER][ORDER + 1];
    __shared__ float hb1[8][2][ORDER], hb2[8][2][ORDER];

    int tid = threadIdx.x;
    int wid = tid >> 5, lane = tid & 31;

    for (int i = tid; i < ORDER * EMB; i += 256) sW1[i] = W1[i];
    for (int i = tid; i < ORDER * ORDER; i += 256) {
        int o = i >> 6, j = i & 63;
        sW2T[j][o] = W2[i];
        sW3T[j][o] = W3[i];
    }
    if (tid < ORDER) { sb1[tid] = b1[tid]; sb2[tid] = b2[tid]; sb3[tid] = b3[tid]; sfreq[tid] = freq[tid]; }
    __syncthreads();

    int lbase = blockIdx.x * 16 + wid * 2;
    int o0 = lane, o1 = lane + 32;
    float f0 = sfreq[o0], f1 = sfreq[o1];

    // layer 1
    float a0[2], a1[2];
#pragma unroll
    for (int rr = 0; rr < 2; rr++) { a0[rr] = sb1[o0]; a1[rr] = sb1[o1]; }
#pragma unroll
    for (int e = 0; e < EMB; e++) {
        float w0 = sW1[o0 * EMB + e], w1 = sW1[o1 * EMB + e];
#pragma unroll
        for (int rr = 0; rr < 2; rr++) {
            float zv = z[(lbase + rr) * EMB + e];   // broadcast within warp
            a0[rr] += zv * w0;
            a1[rr] += zv * w1;
        }
    }
#pragma unroll
    for (int rr = 0; rr < 2; rr++) {
        hb1[wid][rr][o0] = __sinf(f0 * a0[rr]);
        hb1[wid][rr][o1] = __sinf(f1 * a1[rr]);
    }
    __syncwarp();

    // layer 2
#pragma unroll
    for (int rr = 0; rr < 2; rr++) { a0[rr] = sb2[o0]; a1[rr] = sb2[o1]; }
#pragma unroll 8
    for (int j = 0; j < ORDER; j++) {
        float w0 = sW2T[j][o0], w1 = sW2T[j][o1];
#pragma unroll
        for (int rr = 0; rr < 2; rr++) {
            float hj = hb1[wid][rr][j];
            a0[rr] += hj * w0;
            a1[rr] += hj * w1;
        }
    }
#pragma unroll
    for (int rr = 0; rr < 2; rr++) {
        hb2[wid][rr][o0] = __sinf(f0 * a0[rr]);
        hb2[wid][rr][o1] = __sinf(f1 * a1[rr]);
    }
    __syncwarp();

    // layer 3
#pragma unroll
    for (int rr = 0; rr < 2; rr++) { a0[rr] = sb3[o0]; a1[rr] = sb3[o1]; }
#pragma unroll 8
    for (int j = 0; j < ORDER; j++) {
        float w0 = sW3T[j][o0], w1 = sW3T[j][o1];
#pragma unroll
        for (int rr = 0; rr < 2; rr++) {
            float hj = hb2[wid][rr][j];
            a0[rr] += hj * w0;
            a1[rr] += hj * w1;
        }
    }
#pragma unroll
    for (int rr = 0; rr < 2; rr++) {
        g_h3[(lbase + rr) * ORDER + o0] = __sinf(f0 * a0[rr]);
        g_h3[(lbase + rr) * ORDER + o1] = __sinf(f1 * a1[rr]);
    }

    // decay factorization: decay(d,l) = A[d][l>>6] * B[d][l&63]
    for (int g = blockIdx.x * 256 + tid; g < DMODEL * 64; g += MLP_BLOCKS * 256) {
        int i = g & 63;
        float a = fabsf(deltas[g >> 6]);
        g_decayA[g] = __expf(-a * (64.0f * (float)i) * (1.0f / 4095.0f));
        g_decayB[g] = __expf(-a * (float)i * (1.0f / 4095.0f));
    }
    // quarter twiddle table
    for (int g = blockIdx.x * 256 + tid; g < 2048; g += MLP_BLOCKS * 256) {
        float ang = -2.0f * 3.14159265358979323846f * (float)g * (1.0f / 8192.0f);
        float s, c;
        sincosf(ang, &s, &c);
        g_tw[g] = make_float2(c, s);
    }
}

// =====================================================================
// Kernel 2: k[d][l] = (h3[l][:] . W4[d][:]) * decay(d,l)
// =====================================================================
__global__ __launch_bounds__(256) void k_filter_gemm(const float* __restrict__ W4)
{
    __shared__ float sh[64][65];
    __shared__ float sw[64][65];
    int lt = blockIdx.x, dt = blockIdx.y;
    int tid = threadIdx.x;

    for (int i = tid; i < 64 * 64; i += 256) {
        int row = i >> 6, col = i & 63;
        sh[row][col] = g_h3[(lt * 64 + row) * 64 + col];
        sw[row][col] = W4[(dt * 64 + row) * 64 + col];
    }
    __syncthreads();

    int tx = tid & 15, ty = tid >> 4;
    float acc[4][4];
#pragma unroll
    for (int r = 0; r < 4; r++)
#pragma unroll
        for (int c = 0; c < 4; c++) acc[r][c] = 0.0f;

#pragma unroll 8
    for (int o = 0; o < 64; o++) {
        float a[4], b[4];
#pragma unroll
        for (int r = 0; r < 4; r++) a[r] = sh[tx + 16 * r][o];
#pragma unroll
        for (int c = 0; c < 4; c++) b[c] = sw[ty + 16 * c][o];
#pragma unroll
        for (int r = 0; r < 4; r++)
#pragma unroll
            for (int c = 0; c < 4; c++) acc[r][c] += a[r] * b[c];
    }

#pragma unroll
    for (int c = 0; c < 4; c++) {
        int d = dt * 64 + ty + 16 * c;
        float dA = g_decayA[d * 64 + lt];
#pragma unroll
        for (int r = 0; r < 4; r++) {
            int li = tx + 16 * r;
            g_k[(size_t)d * LSEQ + lt * 64 + li] = acc[r][c] * dA * g_decayB[d * 64 + li];
        }
    }
}

// =====================================================================
// Kernel 3: 8192-pt FFT convolution, TWO channels per CTA (grid 512).
// K spectra: one packed FFT of k_{2b} + i*k_{2b+1}; per-channel spectra
// extracted via Hermitian split at product time. Twiddles: round1 = FMA
// chain (table would bank-conflict); round2 + fused phases = smem table
// (warp-broadcast / stride-1, conflict-free). Packed f32x2 butterflies.
// =====================================================================
#define PHI(a) ((a) + ((a) >> 4))
#define ABUF 8704
#define SMEMF2 (2 * 8704 + 8192 + 2048)
#define SLOT(r) ((((r) & 3) << 2) | ((r) >> 2))

typedef unsigned long long c64;   // packed (float x, float y)

__device__ __forceinline__ c64 pk2(float x, float y) {
    c64 u; asm("mov.b64 %0, {%1, %2};" : "=l"(u) : "f"(x), "f"(y)); return u;
}
__device__ __forceinline__ float2 up2(c64 u) {
    float2 v; asm("mov.b64 {%0, %1}, %2;" : "=f"(v.x), "=f"(v.y) : "l"(u)); return v;
}
__device__ __forceinline__ c64 vadd(c64 a, c64 b) {
    c64 r; asm("add.rn.f32x2 %0, %1, %2;" : "=l"(r) : "l"(a), "l"(b)); return r;
}
__device__ __forceinline__ c64 vsub(c64 a, c64 b) {
    c64 r; asm("sub.rn.f32x2 %0, %1, %2;" : "=l"(r) : "l"(a), "l"(b)); return r;
}
__device__ __forceinline__ c64 vmul(c64 a, c64 b) {
    c64 r; asm("mul.rn.f32x2 %0, %1, %2;" : "=l"(r) : "l"(a), "l"(b)); return r;
}
__device__ __forceinline__ c64 vfma(c64 a, c64 b, c64 c) {
    c64 r; asm("fma.rn.f32x2 %0, %1, %2, %3;" : "=l"(r) : "l"(a), "l"(b), "l"(c)); return r;
}
__device__ __forceinline__ c64 vmuli(c64 a)  { float2 v = up2(a); return pk2(-v.y, v.x); }  // +i*a
__device__ __forceinline__ c64 vmulmi(c64 a) { float2 v = up2(a); return pk2(v.y, -v.x); }  // -i*a

// rotate by (cr + i*ci): r = C*a + S*(i*a), C=(cr,cr), S=(ci,ci) packed splats
__device__ __forceinline__ c64 crot(c64 a, c64 C, c64 S) {
    return vfma(S, vmuli(a), vmul(C, a));
}
// apply scalar twiddle (tx + i*ty) to packed value
__device__ __forceinline__ c64 appc(c64 v, float tx, float ty) {
    float2 a = up2(v);
    return pk2(a.x * tx - a.y * ty, a.x * ty + a.y * tx);
}

__device__ __forceinline__ float2 cmul(float2 a, float2 b) {
    return make_float2(a.x * b.x - a.y * b.y, a.x * b.y + a.y * b.x);
}

// W8192^e for e in [0,8192): quarter table + quadrant rotation (branchless-ish)
__device__ __forceinline__ float2 twget2k(const float2* __restrict__ tw, int e) {
    float2 c = tw[e & 2047];
    if (e & 2048) c = make_float2(c.y, -c.x);    // * (-i)
    if (e & 4096) c = make_float2(-c.x, -c.y);   // * (-1)
    return c;
}

#define C16 0.9238795325112867f
#define S16 0.3826834323650898f
#define R2H 0.7071067811865476f

struct PKc {
    c64 C16p, S16n, R2Hp, R2Hn, S16p, C16n;
};

__device__ __forceinline__ void bf4p(c64& x0, c64& x1, c64& x2, c64& x3) {
    c64 t0 = vadd(x0, x2), t1 = vsub(x0, x2);
    c64 t2 = vadd(x1, x3), t3 = vsub(x1, x3);
    c64 u = vmuli(t3);               // i*t3
    x0 = vadd(t0, t2); x2 = vsub(t0, t2);
    x1 = vsub(t1, u);  x3 = vadd(t1, u);
}

__device__ __forceinline__ void bf16p(c64 a[16], const PKc& K) {
    bf4p(a[0], a[4], a[8],  a[12]);
    bf4p(a[1], a[5], a[9],  a[13]);
    bf4p(a[2], a[6], a[10], a[14]);
    bf4p(a[3], a[7], a[11], a[15]);
    a[5]  = crot(a[5],  K.C16p, K.S16n);   // W16^1
    a[9]  = crot(a[9],  K.R2Hp, K.R2Hn);   // W16^2
    a[13] = crot(a[13], K.S16p, K.C16n);   // W16^3
    a[6]  = crot(a[6],  K.R2Hp, K.R2Hn);   // W16^2
    a[10] = vmulmi(a[10]);                 // W16^4
    a[14] = crot(a[14], K.R2Hn, K.R2Hn);   // W16^6
    a[7]  = crot(a[7],  K.S16p, K.C16n);   // W16^3
    a[11] = crot(a[11], K.R2Hn, K.R2Hn);   // W16^6
    a[15] = crot(a[15], K.C16n, K.S16p);   // W16^9
    bf4p(a[0],  a[1],  a[2],  a[3]);
    bf4p(a[4],  a[5],  a[6],  a[7]);
    bf4p(a[8],  a[9],  a[10], a[11]);
    bf4p(a[12], a[13], a[14], a[15]);
}

// Round 1 (SLOG=1): twiddles via per-thread FMA chain (table would conflict).
__device__ __forceinline__ void r16ch1(const float2* __restrict__ src, float2* __restrict__ dst,
                                       float2 wb, int tid, const PKc& K)
{
    c64 a[16];
    const c64* s = reinterpret_cast<const c64*>(src);
    c64* dd = reinterpret_cast<c64*>(dst);
    int lb = tid + (tid >> 4);
#pragma unroll
    for (int j = 0; j < 16; j++) a[j] = s[lb + 544 * j];
    bf16p(a, K);
    float tx = wb.x, ty = wb.y;
    a[SLOT(1)] = appc(a[SLOT(1)], tx, ty);
#pragma unroll
    for (int r = 2; r < 16; r++) {
        float nx = tx * wb.x - ty * wb.y;
        float ny = tx * wb.y + ty * wb.x;
        tx = nx; ty = ny;
        a[SLOT(r)] = appc(a[SLOT(r)], tx, ty);
    }
    int q = tid & 1, p = tid >> 1;
    int ob = q + (p << 5);
#pragma unroll
    for (int r = 0; r < 16; r++) { int ad = ob + (r << 1); dd[ad + (ad >> 4)] = a[SLOT(r)]; }
    __syncthreads();
}

// Round 2 (SLOG=5): sp warp-uniform -> table reads are broadcasts.
__device__ __forceinline__ void r16t2(const float2* __restrict__ src, float2* __restrict__ dst,
                                      const float2* __restrict__ tws, int tid, const PKc& K)
{
    c64 a[16];
    const c64* s = reinterpret_cast<const c64*>(src);
    c64* dd = reinterpret_cast<c64*>(dst);
    int lb = tid + (tid >> 4);
#pragma unroll
    for (int j = 0; j < 16; j++) a[j] = s[lb + 544 * j];
    bf16p(a, K);
    int sp = tid & ~31;
#pragma unroll
    for (int r = 1; r < 16; r++) {
        float2 t = twget2k(tws, r * sp);
        a[SLOT(r)] = appc(a[SLOT(r)], t.x, t.y);
    }
    int q = tid & 31, p = tid >> 5;
    int ob = q + (p << 9);
#pragma unroll
    for (int r = 0; r < 16; r++) { int ad = ob + (r << 5); dd[ad + (ad >> 4)] = a[SLOT(r)]; }
    __syncthreads();
}

// Final round (s=512, p=0, twiddle-free): smem -> registers.
__device__ __forceinline__ void r16_last(const float2* __restrict__ src, c64 a[16], int tid,
                                         const PKc& K)
{
    const c64* s = reinterpret_cast<const c64*>(src);
    int lb = tid + (tid >> 4);
#pragma unroll
    for (int j = 0; j < 16; j++) a[j] = s[lb + 544 * j];
    __syncthreads();     // all reads done: callers may overwrite src after this
    bf16p(a, K);
}

__global__ __launch_bounds__(512, 1) void k_conv(const float* __restrict__ x,
                                                 const float* __restrict__ bias,
                                                 float* __restrict__ out)
{
    extern __shared__ float2 sm[];
    float2* A   = sm;
    float2* B   = sm + ABUF;
    float2* Kb  = sm + 2 * ABUF;          // 8192: packed-pair K spectrum P
    float2* tws = sm + 2 * ABUF + 8192;   // 2048

    int tid = threadIdx.x;
    int d0 = 2 * blockIdx.x, d1 = d0 + 1;

    for (int i = tid; i < 2048; i += 512) tws[i] = g_tw[i];

    PKc K;
    K.C16p = pk2(C16, C16);   K.S16n = pk2(-S16, -S16);
    K.R2Hp = pk2(R2H, R2H);   K.R2Hn = pk2(-R2H, -R2H);
    K.S16p = pk2(S16, S16);   K.C16n = pk2(-C16, -C16);

    // round-1 twiddle base: W8192^(tid&~1)
    float ss, cc;
    sincosf(-3.14159265358979323846f * (float)(tid & ~1) * (1.0f / 4096.0f), &ss, &cc);
    const float2 w1 = make_float2(cc, ss);
    __syncthreads();    // tws ready

    c64 a[16];

    // ---- packed K-pair spectrum: fft(k_{d0} + i*k_{d1}) -> Kb ----
    const float* kg0 = g_k + (size_t)d0 * LSEQ;
    const float* kg1 = g_k + (size_t)d1 * LSEQ;
#pragma unroll
    for (int it = 0; it < 8; it++) {
        int p = tid + it * 512;
        float2 v = make_float2(kg0[p], kg1[p]);
        int o = PHI(2 * p);
        A[o]     = v;
        A[o + 1] = cmul(v, twget2k(tws, p));
    }
    __syncthreads();
    r16ch1(A, B, w1, tid, K);
    r16t2(B, A, tws, tid, K);
    r16_last(A, a, tid, K);
#pragma unroll
    for (int r = 0; r < 16; r++) Kb[tid + 512 * r] = up2(a[SLOT(r)]);

    float bd0 = bias[d0], bd1 = bias[d1];
    const float inv = 1.0f / 16384.0f;    // 1/N * 1/2 (Hermitian-split half)

#pragma unroll
    for (int ch = 0; ch < 2; ch++) {
        int d = ch ? d1 : d0;
        float bd = ch ? bd1 : bd0;
#pragma unroll
        for (int pr = 0; pr < 2; pr++) {
            const float* x0 = x + ((size_t)(2 * pr) * DMODEL + d) * LSEQ;
            const float* x1 = x + ((size_t)(2 * pr + 1) * DMODEL + d) * LSEQ;

            // forward FFT of packed x0 + i*x1: fused radix-2 from global
#pragma unroll
            for (int it = 0; it < 8; it++) {
                int p = tid + it * 512;
                float2 v = make_float2(x0[p], x1[p]);
                int o = PHI(2 * p);
                A[o]     = v;
                A[o + 1] = cmul(v, twget2k(tws, p));
            }
            __syncthreads();
            r16ch1(A, B, w1, tid, K);
            r16t2(B, A, tws, tid, K);
            r16_last(A, a, tid, K);     // W spectrum at tid+512r in regs

            // product with Hermitian-extracted K (x2, no 1/2) + conj + fused r2
#pragma unroll
            for (int r = 0; r < 8; r++) {
                int p = tid + 512 * r;              // [0,4096)
                float2 Pp = Kb[p];
                float2 Pq = Kb[(8192 - p) & 8191];
                float2 Ph = Kb[p + 4096];
                float2 Pg = Kb[4096 - p];           // partner of p+4096
                float2 Kp, Kh;
                if (ch == 0) {
                    Kp = make_float2(Pp.x + Pq.x, Pp.y - Pq.y);
                    Kh = make_float2(Ph.x + Pg.x, Ph.y - Pg.y);
                } else {
                    // -i * (P[p] - conj(P[q]))
                    float2 df = make_float2(Pp.x - Pq.x, Pp.y + Pq.y);
                    Kp = make_float2(df.y, -df.x);
                    float2 dh = make_float2(Ph.x - Pg.x, Ph.y + Pg.y);
                    Kh = make_float2(dh.y, -dh.x);
                }
                float2 Wl = up2(a[SLOT(r)]);
                float2 Wh = up2(a[SLOT(r + 8)]);
                float2 zl = cmul(Wl, Kp); zl.y = -zl.y;
                float2 zh = cmul(Wh, Kh); zh.y = -zh.y;
                float2 s2 = make_float2(zl.x + zh.x, zl.y + zh.y);
                float2 df2 = make_float2(zl.x - zh.x, zl.y - zh.y);
                int o = PHI(2 * p);
                A[o]     = s2;
                A[o + 1] = cmul(df2, twget2k(tws, p));
            }
            __syncthreads();
            r16ch1(A, B, w1, tid, K);
            r16t2(B, A, tws, tid, K);
            r16_last(A, a, tid, K);     // fft(conj Z) at tid+512r in regs

            // ifft = conj(.)/(2N)
            float* o0 = out + ((size_t)(2 * pr) * DMODEL + d) * LSEQ;
            float* o1 = out + ((size_t)(2 * pr + 1) * DMODEL + d) * LSEQ;
#pragma unroll
            for (int r = 0; r < 8; r++) {
                int i = tid + 512 * r;
                float2 y = up2(a[SLOT(r)]);
                o0[i] =  y.x * inv + x0[i] * bd;
                o1[i] = -y.y * inv + x1[i] * bd;
            }
        }
    }
}

// =====================================================================
extern "C" void kernel_launch(void* const* d_in, const int* in_sizes, int n_in,
                              void* d_out, int out_size)
{
    (void)n_in; (void)out_size;
    const float* x = (const float*)d_in[0];
    int base = (in_sizes[1] == 1) ? 2 : 1;
    const float* z      = (const float*)d_in[base + 0];
    const float* deltas = (const float*)d_in[base + 2];
    const float* W1     = (const float*)d_in[base + 3];
    const float* b1     = (const float*)d_in[base + 4];
    const float* freq   = (const float*)d_in[base + 5];
    const float* W2     = (const float*)d_in[base + 6];
    const float* b2     = (const float*)d_in[base + 7];
    const float* W3     = (const float*)d_in[base + 8];
    const float* b3     = (const float*)d_in[base + 9];
    const float* W4     = (const float*)d_in[base + 10];
    const float* bias   = (const float*)d_in[base + 11];
    float* out = (float*)d_out;

    k_filter_mlp<<<MLP_BLOCKS, 256>>>(z, deltas, W1, b1, freq, W2, b2, W3, b3);

    dim3 g2(64, 16);
    k_filter_gemm<<<g2, 256>>>(W4);

    const int smem_bytes = SMEMF2 * (int)sizeof(float2);   // 221,184 B
    cudaFuncSetAttribute(k_conv, cudaFuncAttributeMaxDynamicSharedMemorySize, smem_bytes);
    k_conv<<<DMODEL / 2, 512, smem_bytes>>>(x, bias, out);
}

// round 11
// speedup vs baseline: 1.0725x; 1.0725x over previous
#include <cuda_runtime.h>
#include <math.h>

#define LSEQ   4096
#define DMODEL 1024
#define ORDER  64
#define EMB    5

// ---- scratch (static device globals: allowed) ----
__device__ float  g_h3[LSEQ * ORDER];
__device__ float  g_k [DMODEL * LSEQ];
__device__ float  g_decayA[DMODEL * 64];
__device__ float  g_decayB[DMODEL * 64];
__device__ float2 g_tw[2048];   // quarter table of W8192: w[j]=exp(-2*pi*i*j/8192)

// =====================================================================
// Kernel 1: implicit-filter MLP. 2 rows per warp, 8 warps -> 16 rows/CTA.
// grid 256. Also fills decay + twiddle tables.
// =====================================================================
#define MLP_BLOCKS 256
__global__ __launch_bounds__(256) void k_filter_mlp(
    const float* __restrict__ z, const float* __restrict__ deltas,
    const float* __restrict__ W1, const float* __restrict__ b1,
    const float* __restrict__ freq, const float* __restrict__ W2,
    const float* __restrict__ b2, const float* __restrict__ W3,
    const float* __restrict__ b3)
{
    __shared__ float sW1[ORDER * EMB], sb1[ORDER], sb2[ORDER], sb3[ORDER], sfreq[ORDER];
    __shared__ float sW2T[ORDER][ORDER + 1];   // transposed: [j][o]
    __shared__ float sW3T[ORDER][ORDER + 1];
    __shared__ float hb1[8][2][ORDER], hb2[8][2][ORDER];

    int tid = threadIdx.x;
    int wid = tid >> 5, lane = tid & 31;

    for (int i = tid; i < ORDER * EMB; i += 256) sW1[i] = W1[i];
    for (int i = tid; i < ORDER * ORDER; i += 256) {
        int o = i >> 6, j = i & 63;
        sW2T[j][o] = W2[i];
        sW3T[j][o] = W3[i];
    }
    if (tid < ORDER) { sb1[tid] = b1[tid]; sb2[tid] = b2[tid]; sb3[tid] = b3[tid]; sfreq[tid] = freq[tid]; }
    __syncthreads();

    int lbase = blockIdx.x * 16 + wid * 2;
    int o0 = lane, o1 = lane + 32;
    float f0 = sfreq[o0], f1 = sfreq[o1];

    // layer 1
    float a0[2], a1[2];
#pragma unroll
    for (int rr = 0; rr < 2; rr++) { a0[rr] = sb1[o0]; a1[rr] = sb1[o1]; }
#pragma unroll
    for (int e = 0; e < EMB; e++) {
        float w0 = sW1[o0 * EMB + e], w1 = sW1[o1 * EMB + e];
#pragma unroll
        for (int rr = 0; rr < 2; rr++) {
            float zv = z[(lbase + rr) * EMB + e];   // broadcast within warp
            a0[rr] += zv * w0;
            a1[rr] += zv * w1;
        }
    }
#pragma unroll
    for (int rr = 0; rr < 2; rr++) {
        hb1[wid][rr][o0] = __sinf(f0 * a0[rr]);
        hb1[wid][rr][o1] = __sinf(f1 * a1[rr]);
    }
    __syncwarp();

    // layer 2
#pragma unroll
    for (int rr = 0; rr < 2; rr++) { a0[rr] = sb2[o0]; a1[rr] = sb2[o1]; }
#pragma unroll 8
    for (int j = 0; j < ORDER; j++) {
        float w0 = sW2T[j][o0], w1 = sW2T[j][o1];
#pragma unroll
        for (int rr = 0; rr < 2; rr++) {
            float hj = hb1[wid][rr][j];
            a0[rr] += hj * w0;
            a1[rr] += hj * w1;
        }
    }
#pragma unroll
    for (int rr = 0; rr < 2; rr++) {
        hb2[wid][rr][o0] = __sinf(f0 * a0[rr]);
        hb2[wid][rr][o1] = __sinf(f1 * a1[rr]);
    }
    __syncwarp();

    // layer 3
#pragma unroll
    for (int rr = 0; rr < 2; rr++) { a0[rr] = sb3[o0]; a1[rr] = sb3[o1]; }
#pragma unroll 8
    for (int j = 0; j < ORDER; j++) {
        float w0 = sW3T[j][o0], w1 = sW3T[j][o1];
#pragma unroll
        for (int rr = 0; rr < 2; rr++) {
            float hj = hb2[wid][rr][j];
            a0[rr] += hj * w0;
            a1[rr] += hj * w1;
        }
    }
#pragma unroll
    for (int rr = 0; rr < 2; rr++) {
        g_h3[(lbase + rr) * ORDER + o0] = __sinf(f0 * a0[rr]);
        g_h3[(lbase + rr) * ORDER + o1] = __sinf(f1 * a1[rr]);
    }

    // decay factorization: decay(d,l) = A[d][l>>6] * B[d][l&63]
    for (int g = blockIdx.x * 256 + tid; g < DMODEL * 64; g += MLP_BLOCKS * 256) {
        int i = g & 63;
        float a = fabsf(deltas[g >> 6]);
        g_decayA[g] = __expf(-a * (64.0f * (float)i) * (1.0f / 4095.0f));
        g_decayB[g] = __expf(-a * (float)i * (1.0f / 4095.0f));
    }
    // quarter twiddle table
    for (int g = blockIdx.x * 256 + tid; g < 2048; g += MLP_BLOCKS * 256) {
        float ang = -2.0f * 3.14159265358979323846f * (float)g * (1.0f / 8192.0f);
        float s, c;
        sincosf(ang, &s, &c);
        g_tw[g] = make_float2(c, s);
    }
}

// =====================================================================
// Kernel 2: k[d][l] = (h3[l][:] . W4[d][:]) * decay(d,l)
// =====================================================================
__global__ __launch_bounds__(256) void k_filter_gemm(const float* __restrict__ W4)
{
    __shared__ float sh[64][65];
    __shared__ float sw[64][65];
    int lt = blockIdx.x, dt = blockIdx.y;
    int tid = threadIdx.x;

    for (int i = tid; i < 64 * 64; i += 256) {
        int row = i >> 6, col = i & 63;
        sh[row][col] = g_h3[(lt * 64 + row) * 64 + col];
        sw[row][col] = W4[(dt * 64 + row) * 64 + col];
    }
    __syncthreads();

    int tx = tid & 15, ty = tid >> 4;
    float acc[4][4];
#pragma unroll
    for (int r = 0; r < 4; r++)
#pragma unroll
        for (int c = 0; c < 4; c++) acc[r][c] = 0.0f;

#pragma unroll 8
    for (int o = 0; o < 64; o++) {
        float a[4], b[4];
#pragma unroll
        for (int r = 0; r < 4; r++) a[r] = sh[tx + 16 * r][o];
#pragma unroll
        for (int c = 0; c < 4; c++) b[c] = sw[ty + 16 * c][o];
#pragma unroll
        for (int r = 0; r < 4; r++)
#pragma unroll
            for (int c = 0; c < 4; c++) acc[r][c] += a[r] * b[c];
    }

#pragma unroll
    for (int c = 0; c < 4; c++) {
        int d = dt * 64 + ty + 16 * c;
        float dA = g_decayA[d * 64 + lt];
#pragma unroll
        for (int r = 0; r < 4; r++) {
            int li = tx + 16 * r;
            g_k[(size_t)d * LSEQ + lt * 64 + li] = acc[r][c] * dA * g_decayB[d * 64 + li];
        }
    }
}

// =====================================================================
// Kernel 3: per-channel 8192-pt FFT convolution (R9 structure, grid 1024).
// 8192 = 2*16^3: radix-2 fused into loads/product; 3 radix-16 rounds
// (ping-pong A/B), final round ends in registers. Twiddles:
//   round 1   -> per-thread FMA chain (table access would bank-conflict)
//   round 2   -> smem table, warp-uniform exponent = pure LDS broadcast
//   fused r2 / product -> smem table, stride-1 = conflict-free
// Butterfly core uses packed f32x2 (FADD2/FFMA2).
// =====================================================================
#define PHI(a) ((a) + ((a) >> 4))
#define ABUF 8704
#define SMEMF2 (2 * 8704 + 8192 + 2048)
#define SLOT(r) ((((r) & 3) << 2) | ((r) >> 2))

typedef unsigned long long c64;   // packed (float x, float y)

__device__ __forceinline__ c64 pk2(float x, float y) {
    c64 u; asm("mov.b64 %0, {%1, %2};" : "=l"(u) : "f"(x), "f"(y)); return u;
}
__device__ __forceinline__ float2 up2(c64 u) {
    float2 v; asm("mov.b64 {%0, %1}, %2;" : "=f"(v.x), "=f"(v.y) : "l"(u)); return v;
}
__device__ __forceinline__ c64 vadd(c64 a, c64 b) {
    c64 r; asm("add.rn.f32x2 %0, %1, %2;" : "=l"(r) : "l"(a), "l"(b)); return r;
}
__device__ __forceinline__ c64 vsub(c64 a, c64 b) {
    c64 r; asm("sub.rn.f32x2 %0, %1, %2;" : "=l"(r) : "l"(a), "l"(b)); return r;
}
__device__ __forceinline__ c64 vmul(c64 a, c64 b) {
    c64 r; asm("mul.rn.f32x2 %0, %1, %2;" : "=l"(r) : "l"(a), "l"(b)); return r;
}
__device__ __forceinline__ c64 vfma(c64 a, c64 b, c64 c) {
    c64 r; asm("fma.rn.f32x2 %0, %1, %2, %3;" : "=l"(r) : "l"(a), "l"(b), "l"(c)); return r;
}
__device__ __forceinline__ c64 vmuli(c64 a)  { float2 v = up2(a); return pk2(-v.y, v.x); }  // +i*a
__device__ __forceinline__ c64 vmulmi(c64 a) { float2 v = up2(a); return pk2(v.y, -v.x); }  // -i*a

// rotate by (cr + i*ci): r = C*a + S*(i*a), C=(cr,cr), S=(ci,ci) packed splats
__device__ __forceinline__ c64 crot(c64 a, c64 C, c64 S) {
    return vfma(S, vmuli(a), vmul(C, a));
}
// apply scalar twiddle (tx + i*ty) to packed value
__device__ __forceinline__ c64 appc(c64 v, float tx, float ty) {
    float2 a = up2(v);
    return pk2(a.x * tx - a.y * ty, a.x * ty + a.y * tx);
}

__device__ __forceinline__ float2 cmul(float2 a, float2 b) {
    return make_float2(a.x * b.x - a.y * b.y, a.x * b.y + a.y * b.x);
}

// W8192^e for e in [0,8192): quarter table + quadrant rotation
__device__ __forceinline__ float2 twget2k(const float2* __restrict__ tw, int e) {
    float2 c = tw[e & 2047];
    if (e & 2048) c = make_float2(c.y, -c.x);    // * (-i)
    if (e & 4096) c = make_float2(-c.x, -c.y);   // * (-1)
    return c;
}

#define C16 0.9238795325112867f
#define S16 0.3826834323650898f
#define R2H 0.7071067811865476f

struct PKc {
    c64 C16p, S16n, R2Hp, R2Hn, S16p, C16n;
};

__device__ __forceinline__ void bf4p(c64& x0, c64& x1, c64& x2, c64& x3) {
    c64 t0 = vadd(x0, x2), t1 = vsub(x0, x2);
    c64 t2 = vadd(x1, x3), t3 = vsub(x1, x3);
    c64 u = vmuli(t3);               // i*t3
    x0 = vadd(t0, t2); x2 = vsub(t0, t2);
    x1 = vsub(t1, u);  x3 = vadd(t1, u);
}

__device__ __forceinline__ void bf16p(c64 a[16], const PKc& K) {
    bf4p(a[0], a[4], a[8],  a[12]);
    bf4p(a[1], a[5], a[9],  a[13]);
    bf4p(a[2], a[6], a[10], a[14]);
    bf4p(a[3], a[7], a[11], a[15]);
    a[5]  = crot(a[5],  K.C16p, K.S16n);   // W16^1
    a[9]  = crot(a[9],  K.R2Hp, K.R2Hn);   // W16^2
    a[13] = crot(a[13], K.S16p, K.C16n);   // W16^3
    a[6]  = crot(a[6],  K.R2Hp, K.R2Hn);   // W16^2
    a[10] = vmulmi(a[10]);                 // W16^4
    a[14] = crot(a[14], K.R2Hn, K.R2Hn);   // W16^6
    a[7]  = crot(a[7],  K.S16p, K.C16n);   // W16^3
    a[11] = crot(a[11], K.R2Hn, K.R2Hn);   // W16^6
    a[15] = crot(a[15], K.C16n, K.S16p);   // W16^9
    bf4p(a[0],  a[1],  a[2],  a[3]);
    bf4p(a[4],  a[5],  a[6],  a[7]);
    bf4p(a[8],  a[9],  a[10], a[11]);
    bf4p(a[12], a[13], a[14], a[15]);
}

// Round 1 (SLOG=1): twiddles via per-thread FMA chain (table would conflict).
__device__ __forceinline__ void r16ch1(const float2* __restrict__ src, float2* __restrict__ dst,
                                       float2 wb, int tid, const PKc& K)
{
    c64 a[16];
    const c64* s = reinterpret_cast<const c64*>(src);
    c64* dd = reinterpret_cast<c64*>(dst);
    int lb = tid + (tid >> 4);
#pragma unroll
    for (int j = 0; j < 16; j++) a[j] = s[lb + 544 * j];
    bf16p(a, K);
    float tx = wb.x, ty = wb.y;
    a[SLOT(1)] = appc(a[SLOT(1)], tx, ty);
#pragma unroll
    for (int r = 2; r < 16; r++) {
        float nx = tx * wb.x - ty * wb.y;
        float ny = tx * wb.y + ty * wb.x;
        tx = nx; ty = ny;
        a[SLOT(r)] = appc(a[SLOT(r)], tx, ty);
    }
    int q = tid & 1, p = tid >> 1;
    int ob = q + (p << 5);
#pragma unroll
    for (int r = 0; r < 16; r++) { int ad = ob + (r << 1); dd[ad + (ad >> 4)] = a[SLOT(r)]; }
    __syncthreads();
}

// Round 2 (SLOG=5): sp warp-uniform -> table reads are broadcasts.
__device__ __forceinline__ void r16t2(const float2* __restrict__ src, float2* __restrict__ dst,
                                      const float2* __restrict__ tws, int tid, const PKc& K)
{
    c64 a[16];
    const c64* s = reinterpret_cast<const c64*>(src);
    c64* dd = reinterpret_cast<c64*>(dst);
    int lb = tid + (tid >> 4);
#pragma unroll
    for (int j = 0; j < 16; j++) a[j] = s[lb + 544 * j];
    bf16p(a, K);
    int sp = tid & ~31;
#pragma unroll
    for (int r = 1; r < 16; r++) {
        float2 t = twget2k(tws, r * sp);
        a[SLOT(r)] = appc(a[SLOT(r)], t.x, t.y);
    }
    int q = tid & 31, p = tid >> 5;
    int ob = q + (p << 9);
#pragma unroll
    for (int r = 0; r < 16; r++) { int ad = ob + (r << 5); dd[ad + (ad >> 4)] = a[SLOT(r)]; }
    __syncthreads();
}

// Final round (s=512, p=0, twiddle-free): smem -> registers.
// Value at global index tid + 512*r ends in a[SLOT(r)].
__device__ __forceinline__ void r16_last(const float2* __restrict__ src, c64 a[16], int tid,
                                         const PKc& K)
{
    const c64* s = reinterpret_cast<const c64*>(src);
    int lb = tid + (tid >> 4);
#pragma unroll
    for (int j = 0; j < 16; j++) a[j] = s[lb + 544 * j];
    __syncthreads();     // all reads done: callers may overwrite src after this
    bf16p(a, K);
}

__global__ __launch_bounds__(512, 1) void k_conv(const float* __restrict__ x,
                                                 const float* __restrict__ bias,
                                                 float* __restrict__ out)
{
    extern __shared__ float2 sm[];
    float2* A   = sm;
    float2* B   = sm + ABUF;
    float2* Kb  = sm + 2 * ABUF;          // 8192, per-channel K spectrum
    float2* tws = sm + 2 * ABUF + 8192;   // 2048

    int tid = threadIdx.x;
    int d = blockIdx.x;

    for (int i = tid; i < 2048; i += 512) tws[i] = g_tw[i];

    PKc K;
    K.C16p = pk2(C16, C16);   K.S16n = pk2(-S16, -S16);
    K.R2Hp = pk2(R2H, R2H);   K.R2Hn = pk2(-R2H, -R2H);
    K.S16p = pk2(S16, S16);   K.C16n = pk2(-C16, -C16);

    // round-1 twiddle base: W8192^(tid&~1)
    float ss, cc;
    sincosf(-3.14159265358979323846f * (float)(tid & ~1) * (1.0f / 4096.0f), &ss, &cc);
    const float2 w1 = make_float2(cc, ss);
    __syncthreads();    // tws ready

    c64 a[16];

    // ---- K spectrum: fused radix-2 (zero-padded) + 3 rounds -> Kb ----
    const float* kg = g_k + (size_t)d * LSEQ;
#pragma unroll
    for (int it = 0; it < 8; it++) {
        int p = tid + it * 512;
        float v = kg[p];
        float2 w = twget2k(tws, p);          // stride-1: conflict-free
        int o = PHI(2 * p);
        A[o]     = make_float2(v, 0.0f);
        A[o + 1] = make_float2(v * w.x, v * w.y);
    }
    __syncthreads();
    r16ch1(A, B, w1, tid, K);
    r16t2(B, A, tws, tid, K);
    r16_last(A, a, tid, K);
#pragma unroll
    for (int r = 0; r < 16; r++) Kb[tid + 512 * r] = up2(a[SLOT(r)]);

    float bd = bias[d];
    const float inv = 1.0f / 8192.0f;

#pragma unroll
    for (int pr = 0; pr < 2; pr++) {
        const float* x0 = x + ((size_t)(2 * pr) * DMODEL + d) * LSEQ;
        const float* x1 = x + ((size_t)(2 * pr + 1) * DMODEL + d) * LSEQ;

        // forward FFT of packed x0 + i*x1: fused radix-2 from global
#pragma unroll
        for (int it = 0; it < 8; it++) {
            int p = tid + it * 512;
            float2 v = make_float2(x0[p], x1[p]);
            int o = PHI(2 * p);
            A[o]     = v;
            A[o + 1] = cmul(v, twget2k(tws, p));
        }
        __syncthreads();
        r16ch1(A, B, w1, tid, K);
        r16t2(B, A, tws, tid, K);
        r16_last(A, a, tid, K);         // W spectrum at tid+512r in regs

        // product with K + conj + inverse's fused radix-2 (regs + Kb reads)
#pragma unroll
        for (int r = 0; r < 8; r++) {
            int p = tid + 512 * r;
            float2 Wl = up2(a[SLOT(r)]);
            float2 Wh = up2(a[SLOT(r + 8)]);
            float2 zl = cmul(Wl, Kb[p]);        zl.y = -zl.y;
            float2 zh = cmul(Wh, Kb[p + 4096]); zh.y = -zh.y;
            float2 s2 = make_float2(zl.x + zh.x, zl.y + zh.y);
            float2 df = make_float2(zl.x - zh.x, zl.y - zh.y);
            int o = PHI(2 * p);
            A[o]     = s2;
            A[o + 1] = cmul(df, twget2k(tws, p));
        }
        __syncthreads();
        r16ch1(A, B, w1, tid, K);
        r16t2(B, A, tws, tid, K);
        r16_last(A, a, tid, K);         // fft(conj Z) at tid+512r in regs

        // ifft = conj(.)/N; indices < 4096 are the valid linear-conv part
        float* o0 = out + ((size_t)(2 * pr) * DMODEL + d) * LSEQ;
        float* o1 = out + ((size_t)(2 * pr + 1) * DMODEL + d) * LSEQ;
#pragma unroll
        for (int r = 0; r < 8; r++) {
            int i = tid + 512 * r;
            float2 y = up2(a[SLOT(r)]);
            o0[i] =  y.x * inv + x0[i] * bd;
            o1[i] = -y.y * inv + x1[i] * bd;
        }
    }
}

// =====================================================================
extern "C" void kernel_launch(void* const* d_in, const int* in_sizes, int n_in,
                              void* d_out, int out_size)
{
    (void)n_in; (void)out_size;
    const float* x = (const float*)d_in[0];
    int base = (in_sizes[1] == 1) ? 2 : 1;
    const float* z      = (const float*)d_in[base + 0];
    const float* deltas = (const float*)d_in[base + 2];
    const float* W1     = (const float*)d_in[base + 3];
    const float* b1     = (const float*)d_in[base + 4];
    const float* freq   = (const float*)d_in[base + 5];
    const float* W2     = (const float*)d_in[base + 6];
    const float* b2     = (const float*)d_in[base + 7];
    const float* W3     = (const float*)d_in[base + 8];
    const float* b3     = (const float*)d_in[base + 9];
    const float* W4     = (const float*)d_in[base + 10];
    const float* bias   = (const float*)d_in[base + 11];
    float* out = (float*)d_out;

    k_filter_mlp<<<MLP_BLOCKS, 256>>>(z, deltas, W1, b1, freq, W2, b2, W3, b3);

    dim3 g2(64, 16);
    k_filter_gemm<<<g2, 256>>>(W4);

    const int smem_bytes = SMEMF2 * (int)sizeof(float2);   // 221,184 B
    cudaFuncSetAttribute(k_conv, cudaFuncAttributeMaxDynamicSharedMemorySize, smem_bytes);
    k_conv<<<DMODEL, 512, smem_bytes>>>(x, bias, out);
}

// round 12
// speedup vs baseline: 1.0775x; 1.0046x over previous
#include <cuda_runtime.h>
#include <math.h>

#define LSEQ   4096
#define DMODEL 1024
#define ORDER  64
#define EMB    5

// ---- scratch (static device globals: allowed) ----
__device__ float  g_h3[LSEQ * ORDER];
__device__ float  g_k [DMODEL * LSEQ];
__device__ float  g_decayA[DMODEL * 64];
__device__ float  g_decayB[DMODEL * 64];
__device__ float2 g_tw[2048];   // quarter table of W8192: w[j]=exp(-2*pi*i*j/8192)

// =====================================================================
// Kernel 1: implicit-filter MLP. 2 rows per warp, 8 warps -> 16 rows/CTA.
// grid 256. Accumulators fully scalarized (no indexed arrays -> no
// local-memory traffic). Also fills decay + twiddle tables.
// =====================================================================
#define MLP_BLOCKS 256
__global__ __launch_bounds__(256) void k_filter_mlp(
    const float* __restrict__ z, const float* __restrict__ deltas,
    const float* __restrict__ W1, const float* __restrict__ b1,
    const float* __restrict__ freq, const float* __restrict__ W2,
    const float* __restrict__ b2, const float* __restrict__ W3,
    const float* __restrict__ b3)
{
    __shared__ float sW1[ORDER * EMB], sb1[ORDER], sb2[ORDER], sb3[ORDER], sfreq[ORDER];
    __shared__ float sW2T[ORDER][ORDER + 1];   // transposed: [j][o]
    __shared__ float sW3T[ORDER][ORDER + 1];
    __shared__ float hb1[8][2][ORDER], hb2[8][2][ORDER];

    int tid = threadIdx.x;
    int wid = tid >> 5, lane = tid & 31;

    for (int i = tid; i < ORDER * EMB; i += 256) sW1[i] = W1[i];
    for (int i = tid; i < ORDER * ORDER; i += 256) {
        int o = i >> 6, j = i & 63;
        sW2T[j][o] = W2[i];
        sW3T[j][o] = W3[i];
    }
    if (tid < ORDER) { sb1[tid] = b1[tid]; sb2[tid] = b2[tid]; sb3[tid] = b3[tid]; sfreq[tid] = freq[tid]; }
    __syncthreads();

    int lbase = blockIdx.x * 16 + wid * 2;
    int o0 = lane, o1 = lane + 32;
    float f0 = sfreq[o0], f1 = sfreq[o1];

    // layer 1 (scalar accumulators: a<o><row>)
    float a00 = sb1[o0], a01 = sb1[o0];   // o0: rows 0,1
    float a10 = sb1[o1], a11 = sb1[o1];   // o1: rows 0,1
#pragma unroll
    for (int e = 0; e < EMB; e++) {
        float w0 = sW1[o0 * EMB + e], w1 = sW1[o1 * EMB + e];
        float zv0 = z[lbase * EMB + e];          // broadcast within warp
        float zv1 = z[(lbase + 1) * EMB + e];
        a00 += zv0 * w0;  a01 += zv1 * w0;
        a10 += zv0 * w1;  a11 += zv1 * w1;
    }
    hb1[wid][0][o0] = __sinf(f0 * a00);
    hb1[wid][1][o0] = __sinf(f0 * a01);
    hb1[wid][0][o1] = __sinf(f1 * a10);
    hb1[wid][1][o1] = __sinf(f1 * a11);
    __syncwarp();

    // layer 2
    a00 = sb2[o0]; a01 = sb2[o0];
    a10 = sb2[o1]; a11 = sb2[o1];
#pragma unroll 8
    for (int j = 0; j < ORDER; j++) {
        float w0 = sW2T[j][o0], w1 = sW2T[j][o1];
        float h0 = hb1[wid][0][j];
        float h1 = hb1[wid][1][j];
        a00 += h0 * w0;  a01 += h1 * w0;
        a10 += h0 * w1;  a11 += h1 * w1;
    }
    hb2[wid][0][o0] = __sinf(f0 * a00);
    hb2[wid][1][o0] = __sinf(f0 * a01);
    hb2[wid][0][o1] = __sinf(f1 * a10);
    hb2[wid][1][o1] = __sinf(f1 * a11);
    __syncwarp();

    // layer 3
    a00 = sb3[o0]; a01 = sb3[o0];
    a10 = sb3[o1]; a11 = sb3[o1];
#pragma unroll 8
    for (int j = 0; j < ORDER; j++) {
        float w0 = sW3T[j][o0], w1 = sW3T[j][o1];
        float h0 = hb2[wid][0][j];
        float h1 = hb2[wid][1][j];
        a00 += h0 * w0;  a01 += h1 * w0;
        a10 += h0 * w1;  a11 += h1 * w1;
    }
    g_h3[lbase * ORDER + o0]       = __sinf(f0 * a00);
    g_h3[(lbase + 1) * ORDER + o0] = __sinf(f0 * a01);
    g_h3[lbase * ORDER + o1]       = __sinf(f1 * a10);
    g_h3[(lbase + 1) * ORDER + o1] = __sinf(f1 * a11);

    // decay factorization: decay(d,l) = A[d][l>>6] * B[d][l&63]
    for (int g = blockIdx.x * 256 + tid; g < DMODEL * 64; g += MLP_BLOCKS * 256) {
        int i = g & 63;
        float a = fabsf(deltas[g >> 6]);
        g_decayA[g] = __expf(-a * (64.0f * (float)i) * (1.0f / 4095.0f));
        g_decayB[g] = __expf(-a * (float)i * (1.0f / 4095.0f));
    }
    // quarter twiddle table
    for (int g = blockIdx.x * 256 + tid; g < 2048; g += MLP_BLOCKS * 256) {
        float ang = -2.0f * 3.14159265358979323846f * (float)g * (1.0f / 8192.0f);
        float s, c;
        sincosf(ang, &s, &c);
        g_tw[g] = make_float2(c, s);
    }
}

// =====================================================================
// Kernel 2: k[d][l] = (h3[l][:] . W4[d][:]) * decay(d,l)
// =====================================================================
__global__ __launch_bounds__(256) void k_filter_gemm(const float* __restrict__ W4)
{
    __shared__ float sh[64][65];
    __shared__ float sw[64][65];
    int lt = blockIdx.x, dt = blockIdx.y;
    int tid = threadIdx.x;

    for (int i = tid; i < 64 * 64; i += 256) {
        int row = i >> 6, col = i & 63;
        sh[row][col] = g_h3[(lt * 64 + row) * 64 + col];
        sw[row][col] = W4[(dt * 64 + row) * 64 + col];
    }
    __syncthreads();

    int tx = tid & 15, ty = tid >> 4;
    float acc[4][4];
#pragma unroll
    for (int r = 0; r < 4; r++)
#pragma unroll
        for (int c = 0; c < 4; c++) acc[r][c] = 0.0f;

#pragma unroll 8
    for (int o = 0; o < 64; o++) {
        float a[4], b[4];
#pragma unroll
        for (int r = 0; r < 4; r++) a[r] = sh[tx + 16 * r][o];
#pragma unroll
        for (int c = 0; c < 4; c++) b[c] = sw[ty + 16 * c][o];
#pragma unroll
        for (int r = 0; r < 4; r++)
#pragma unroll
            for (int c = 0; c < 4; c++) acc[r][c] += a[r] * b[c];
    }

#pragma unroll
    for (int c = 0; c < 4; c++) {
        int d = dt * 64 + ty + 16 * c;
        float dA = g_decayA[d * 64 + lt];
#pragma unroll
        for (int r = 0; r < 4; r++) {
            int li = tx + 16 * r;
            g_k[(size_t)d * LSEQ + lt * 64 + li] = acc[r][c] * dA * g_decayB[d * 64 + li];
        }
    }
}

// =====================================================================
// Kernel 3: per-channel 8192-pt FFT convolution (grid 1024).
// 8192 = 2*16^3: radix-2 fused into loads/product (now 128-bit stores);
// 3 radix-16 rounds (ping-pong A/B), final round ends in registers.
// Padding phi(a) = a + 2*(a>>5): conflict-free AND keeps adjacent pairs
// 16B-aligned so fused phases use STS.128. Twiddles: round1 FMA chain,
// round2 broadcast table, fused phases stride-1 table. Packed f32x2 core.
// =====================================================================
#define PHI2(a) ((a) + (((a) >> 5) << 1))
#define ABUF 8704
#define SMEMF2 (2 * 8704 + 8192 + 2048)
#define SLOT(r) ((((r) & 3) << 2) | ((r) >> 2))

typedef unsigned long long c64;   // packed (float x, float y)

__device__ __forceinline__ c64 pk2(float x, float y) {
    c64 u; asm("mov.b64 %0, {%1, %2};" : "=l"(u) : "f"(x), "f"(y)); return u;
}
__device__ __forceinline__ float2 up2(c64 u) {
    float2 v; asm("mov.b64 {%0, %1}, %2;" : "=f"(v.x), "=f"(v.y) : "l"(u)); return v;
}
__device__ __forceinline__ c64 vadd(c64 a, c64 b) {
    c64 r; asm("add.rn.f32x2 %0, %1, %2;" : "=l"(r) : "l"(a), "l"(b)); return r;
}
__device__ __forceinline__ c64 vsub(c64 a, c64 b) {
    c64 r; asm("sub.rn.f32x2 %0, %1, %2;" : "=l"(r) : "l"(a), "l"(b)); return r;
}
__device__ __forceinline__ c64 vmul(c64 a, c64 b) {
    c64 r; asm("mul.rn.f32x2 %0, %1, %2;" : "=l"(r) : "l"(a), "l"(b)); return r;
}
__device__ __forceinline__ c64 vfma(c64 a, c64 b, c64 c) {
    c64 r; asm("fma.rn.f32x2 %0, %1, %2, %3;" : "=l"(r) : "l"(a), "l"(b), "l"(c)); return r;
}
__device__ __forceinline__ c64 vmuli(c64 a)  { float2 v = up2(a); return pk2(-v.y, v.x); }  // +i*a
__device__ __forceinline__ c64 vmulmi(c64 a) { float2 v = up2(a); return pk2(v.y, -v.x); }  // -i*a

// rotate by (cr + i*ci): r = C*a + S*(i*a), C=(cr,cr), S=(ci,ci) packed splats
__device__ __forceinline__ c64 crot(c64 a, c64 C, c64 S) {
    return vfma(S, vmuli(a), vmul(C, a));
}
// apply scalar twiddle (tx + i*ty) to packed value
__device__ __forceinline__ c64 appc(c64 v, float tx, float ty) {
    float2 a = up2(v);
    return pk2(a.x * tx - a.y * ty, a.x * ty + a.y * tx);
}

__device__ __forceinline__ float2 cmul(float2 a, float2 b) {
    return make_float2(a.x * b.x - a.y * b.y, a.x * b.y + a.y * b.x);
}

// W8192^e for e in [0,8192): quarter table + quadrant rotation
__device__ __forceinline__ float2 twget2k(const float2* __restrict__ tw, int e) {
    float2 c = tw[e & 2047];
    if (e & 2048) c = make_float2(c.y, -c.x);    // * (-i)
    if (e & 4096) c = make_float2(-c.x, -c.y);   // * (-1)
    return c;
}

#define C16 0.9238795325112867f
#define S16 0.3826834323650898f
#define R2H 0.7071067811865476f

struct PKc {
    c64 C16p, S16n, R2Hp, R2Hn, S16p, C16n;
};

__device__ __forceinline__ void bf4p(c64& x0, c64& x1, c64& x2, c64& x3) {
    c64 t0 = vadd(x0, x2), t1 = vsub(x0, x2);
    c64 t2 = vadd(x1, x3), t3 = vsub(x1, x3);
    c64 u = vmuli(t3);               // i*t3
    x0 = vadd(t0, t2); x2 = vsub(t0, t2);
    x1 = vsub(t1, u);  x3 = vadd(t1, u);
}

__device__ __forceinline__ void bf16p(c64 a[16], const PKc& K) {
    bf4p(a[0], a[4], a[8],  a[12]);
    bf4p(a[1], a[5], a[9],  a[13]);
    bf4p(a[2], a[6], a[10], a[14]);
    bf4p(a[3], a[7], a[11], a[15]);
    a[5]  = crot(a[5],  K.C16p, K.S16n);   // W16^1
    a[9]  = crot(a[9],  K.R2Hp, K.R2Hn);   // W16^2
    a[13] = crot(a[13], K.S16p, K.C16n);   // W16^3
    a[6]  = crot(a[6],  K.R2Hp, K.R2Hn);   // W16^2
    a[10] = vmulmi(a[10]);                 // W16^4
    a[14] = crot(a[14], K.R2Hn, K.R2Hn);   // W16^6
    a[7]  = crot(a[7],  K.S16p, K.C16n);   // W16^3
    a[11] = crot(a[11], K.R2Hn, K.R2Hn);   // W16^6
    a[15] = crot(a[15], K.C16n, K.S16p);   // W16^9
    bf4p(a[0],  a[1],  a[2],  a[3]);
    bf4p(a[4],  a[5],  a[6],  a[7]);
    bf4p(a[8],  a[9],  a[10], a[11]);
    bf4p(a[12], a[13], a[14], a[15]);
}

// Round 1 (SLOG=1): twiddles via per-thread FMA chain (table would conflict).
__device__ __forceinline__ void r16ch1(const float2* __restrict__ src, float2* __restrict__ dst,
                                       float2 wb, int tid, const PKc& K)
{
    c64 a[16];
    const c64* s = reinterpret_cast<const c64*>(src);
    c64* dd = reinterpret_cast<c64*>(dst);
    int lb = PHI2(tid);
#pragma unroll
    for (int j = 0; j < 16; j++) a[j] = s[lb + 544 * j];
    bf16p(a, K);
    float tx = wb.x, ty = wb.y;
    a[SLOT(1)] = appc(a[SLOT(1)], tx, ty);
#pragma unroll
    for (int r = 2; r < 16; r++) {
        float nx = tx * wb.x - ty * wb.y;
        float ny = tx * wb.y + ty * wb.x;
        tx = nx; ty = ny;
        a[SLOT(r)] = appc(a[SLOT(r)], tx, ty);
    }
    int q = tid & 1, p = tid >> 1;
    int ob = q + (p << 5);
#pragma unroll
    for (int r = 0; r < 16; r++) { int ad = ob + (r << 1); dd[PHI2(ad)] = a[SLOT(r)]; }
    __syncthreads();
}

// Round 2 (SLOG=5): sp warp-uniform -> table reads are broadcasts.
__device__ __forceinline__ void r16t2(const float2* __restrict__ src, float2* __restrict__ dst,
                                      const float2* __restrict__ tws, int tid, const PKc& K)
{
    c64 a[16];
    const c64* s = reinterpret_cast<const c64*>(src);
    c64* dd = reinterpret_cast<c64*>(dst);
    int lb = PHI2(tid);
#pragma unroll
    for (int j = 0; j < 16; j++) a[j] = s[lb + 544 * j];
    bf16p(a, K);
    int sp = tid & ~31;
#pragma unroll
    for (int r = 1; r < 16; r++) {
        float2 t = twget2k(tws, r * sp);
        a[SLOT(r)] = appc(a[SLOT(r)], t.x, t.y);
    }
    int q = tid & 31, p = tid >> 5;
    int ob = q + (p << 9);
#pragma unroll
    for (int r = 0; r < 16; r++) { int ad = ob + (r << 5); dd[PHI2(ad)] = a[SLOT(r)]; }
    __syncthreads();
}

// Final round (s=512, p=0, twiddle-free): smem -> registers.
// Value at global index tid + 512*r ends in a[SLOT(r)].
__device__ __forceinline__ void r16_last(const float2* __restrict__ src, c64 a[16], int tid,
                                         const PKc& K)
{
    const c64* s = reinterpret_cast<const c64*>(src);
    int lb = PHI2(tid);
#pragma unroll
    for (int j = 0; j < 16; j++) a[j] = s[lb + 544 * j];
    __syncthreads();     // all reads done: callers may overwrite src after this
    bf16p(a, K);
}

__global__ __launch_bounds__(512, 1) void k_conv(const float* __restrict__ x,
                                                 const float* __restrict__ bias,
                                                 float* __restrict__ out)
{
    extern __shared__ float2 sm[];
    float2* A   = sm;
    float2* B   = sm + ABUF;
    float2* Kb  = sm + 2 * ABUF;          // 8192, per-channel K spectrum
    float2* tws = sm + 2 * ABUF + 8192;   // 2048
    float4* A4  = reinterpret_cast<float4*>(A);

    int tid = threadIdx.x;
    int d = blockIdx.x;

    for (int i = tid; i < 2048; i += 512) tws[i] = g_tw[i];

    PKc K;
    K.C16p = pk2(C16, C16);   K.S16n = pk2(-S16, -S16);
    K.R2Hp = pk2(R2H, R2H);   K.R2Hn = pk2(-R2H, -R2H);
    K.S16p = pk2(S16, S16);   K.C16n = pk2(-C16, -C16);

    // round-1 twiddle base: W8192^(tid&~1)
    float ss, cc;
    sincosf(-3.14159265358979323846f * (float)(tid & ~1) * (1.0f / 4096.0f), &ss, &cc);
    const float2 w1 = make_float2(cc, ss);
    __syncthreads();    // tws ready

    c64 a[16];

    // ---- K spectrum: fused radix-2 (zero-padded) + 3 rounds -> Kb ----
    const float* kg = g_k + (size_t)d * LSEQ;
#pragma unroll
    for (int it = 0; it < 8; it++) {
        int p = tid + it * 512;
        float v = kg[p];
        float2 w = twget2k(tws, p);          // stride-1: conflict-free
        A4[PHI2(2 * p) >> 1] = make_float4(v, 0.0f, v * w.x, v * w.y);
    }
    __syncthreads();
    r16ch1(A, B, w1, tid, K);
    r16t2(B, A, tws, tid, K);
    r16_last(A, a, tid, K);
#pragma unroll
    for (int r = 0; r < 16; r++) Kb[tid + 512 * r] = up2(a[SLOT(r)]);

    float bd = bias[d];
    const float inv = 1.0f / 8192.0f;

#pragma unroll
    for (int pr = 0; pr < 2; pr++) {
        const float* x0 = x + ((size_t)(2 * pr) * DMODEL + d) * LSEQ;
        const float* x1 = x + ((size_t)(2 * pr + 1) * DMODEL + d) * LSEQ;

        // forward FFT of packed x0 + i*x1: fused radix-2 from global
#pragma unroll
        for (int it = 0; it < 8; it++) {
            int p = tid + it * 512;
            float2 v = make_float2(x0[p], x1[p]);
            float2 t = twget2k(tws, p);
            float2 vw = cmul(v, t);
            A4[PHI2(2 * p) >> 1] = make_float4(v.x, v.y, vw.x, vw.y);
        }
        __syncthreads();
        r16ch1(A, B, w1, tid, K);
        r16t2(B, A, tws, tid, K);
        r16_last(A, a, tid, K);         // W spectrum at tid+512r in regs

        // product with K + conj + inverse's fused radix-2 (regs + Kb reads)
#pragma unroll
        for (int r = 0; r < 8; r++) {
            int p = tid + 512 * r;
            float2 Wl = up2(a[SLOT(r)]);
            float2 Wh = up2(a[SLOT(r + 8)]);
            float2 zl = cmul(Wl, Kb[p]);        zl.y = -zl.y;
            float2 zh = cmul(Wh, Kb[p + 4096]); zh.y = -zh.y;
            float2 s2 = make_float2(zl.x + zh.x, zl.y + zh.y);
            float2 df = make_float2(zl.x - zh.x, zl.y - zh.y);
            float2 t = twget2k(tws, p);
            float2 dt2 = cmul(df, t);
            A4[PHI2(2 * p) >> 1] = make_float4(s2.x, s2.y, dt2.x, dt2.y);
        }
        __syncthreads();
        r16ch1(A, B, w1, tid, K);
        r16t2(B, A, tws, tid, K);
        r16_last(A, a, tid, K);         // fft(conj Z) at tid+512r in regs

        // ifft = conj(.)/N; indices < 4096 are the valid linear-conv part
        float* o0 = out + ((size_t)(2 * pr) * DMODEL + d) * LSEQ;
        float* o1 = out + ((size_t)(2 * pr + 1) * DMODEL + d) * LSEQ;
#pragma unroll
        for (int r = 0; r < 8; r++) {
            int i = tid + 512 * r;
            float2 y = up2(a[SLOT(r)]);
            o0[i] =  y.x * inv + x0[i] * bd;
            o1[i] = -y.y * inv + x1[i] * bd;
        }
    }
}

// =====================================================================
extern "C" void kernel_launch(void* const* d_in, const int* in_sizes, int n_in,
                              void* d_out, int out_size)
{
    (void)n_in; (void)out_size;
    const float* x = (const float*)d_in[0];
    int base = (in_sizes[1] == 1) ? 2 : 1;
    const float* z      = (const float*)d_in[base + 0];
    const float* deltas = (const float*)d_in[base + 2];
    const float* W1     = (const float*)d_in[base + 3];
    const float* b1     = (const float*)d_in[base + 4];
    const float* freq   = (const float*)d_in[base + 5];
    const float* W2     = (const float*)d_in[base + 6];
    const float* b2     = (const float*)d_in[base + 7];
    const float* W3     = (const float*)d_in[base + 8];
    const float* b3     = (const float*)d_in[base + 9];
    const float* W4     = (const float*)d_in[base + 10];
    const float* bias   = (const float*)d_in[base + 11];
    float* out = (float*)d_out;

    k_filter_mlp<<<MLP_BLOCKS, 256>>>(z, deltas, W1, b1, freq, W2, b2, W3, b3);

    dim3 g2(64, 16);
    k_filter_gemm<<<g2, 256>>>(W4);

    const int smem_bytes = SMEMF2 * (int)sizeof(float2);   // 221,184 B
    cudaFuncSetAttribute(k_conv, cudaFuncAttributeMaxDynamicSharedMemorySize, smem_bytes);
    k_conv<<<DMODEL, 512, smem_bytes>>>(x, bias, out);
}